// round 1
// baseline (speedup 1.0000x reference)
#include <cuda_runtime.h>
#include <cuda_bf16.h>

#define NN 50000
#define NE 800000
#define INF 256
#define HD 256      // H * D = 4 * 64
#define H 4
#define D 64
#define NEG_SLOPE 0.2f

// ---------------- scratch (static device globals; no runtime alloc) ----------------
__device__ float g_ft[NN * HD];        // node projection [N, 256]
__device__ float g_el[NN * H];
__device__ float g_er[NN * H];
__device__ float g_ee[8 * H];          // per-edge-type attention term
__device__ int   g_deg[NN];
__device__ int   g_off[NN];
__device__ int   g_cur[NN];
__device__ int   g_eids[NE];

// ---------------- ee table: ee[t,h] = sum_f (sum_k emb[t,k] W_e[k, h*64+f]) * attn_e[h,f]
__global__ void k_ee(const float* __restrict__ edge_emb,
                     const float* __restrict__ W_e,
                     const float* __restrict__ attn_e) {
    int w = threadIdx.x >> 5;          // 32 warps: (t, h) pairs
    int lane = threadIdx.x & 31;
    if (w >= 32) return;
    int t = w >> 2, h = w & 3;
    float acc0 = 0.f, acc1 = 0.f;
    int f0 = lane, f1 = lane + 32;
    #pragma unroll 4
    for (int k = 0; k < 64; k++) {
        float ek = edge_emb[t * 64 + k];
        acc0 += ek * W_e[k * 256 + h * 64 + f0];
        acc1 += ek * W_e[k * 256 + h * 64 + f1];
    }
    float v = acc0 * attn_e[h * 64 + f0] + acc1 * attn_e[h * 64 + f1];
    #pragma unroll
    for (int o = 16; o > 0; o >>= 1) v += __shfl_xor_sync(0xffffffffu, v, o);
    if (lane == 0) g_ee[t * 4 + h] = v;
}

// ---------------- SGEMM: g_ft = feat[M,256] @ W_fc[256,256] ----------------
__global__ __launch_bounds__(256) void k_gemm(const float* __restrict__ A,
                                              const float* __restrict__ B) {
    const int BM = 128, BN = 64, BK = 16;
    __shared__ float As[BK][BM + 4];   // padded; row stride 132 floats (16B-aligned rows)
    __shared__ float Bs[BK][BN];
    int tid = threadIdx.x;
    int bm = blockIdx.y * BM, bn = blockIdx.x * BN;
    int tx = tid & 15, ty = tid >> 4;

    float acc[8][4];
    #pragma unroll
    for (int i = 0; i < 8; i++)
        #pragma unroll
        for (int j = 0; j < 4; j++) acc[i][j] = 0.f;

    for (int k0 = 0; k0 < 256; k0 += BK) {
        // load A tile: 128 rows x 16 k = 512 float4, 2 per thread
        #pragma unroll
        for (int q = tid; q < 512; q += 256) {
            int r = q >> 2, c4 = q & 3;
            int gr = bm + r;
            float4 v = make_float4(0.f, 0.f, 0.f, 0.f);
            if (gr < NN) v = *(const float4*)(A + gr * 256 + k0 + c4 * 4);
            As[c4 * 4 + 0][r] = v.x;
            As[c4 * 4 + 1][r] = v.y;
            As[c4 * 4 + 2][r] = v.z;
            As[c4 * 4 + 3][r] = v.w;
        }
        // load B tile: 16 x 64 = 256 float4, 1 per thread
        {
            int r = tid >> 4, c4 = tid & 15;
            float4 v = *(const float4*)(B + (k0 + r) * 256 + bn + c4 * 4);
            *(float4*)&Bs[r][c4 * 4] = v;
        }
        __syncthreads();
        #pragma unroll
        for (int kk = 0; kk < BK; kk++) {
            float4 a0 = *(const float4*)&As[kk][ty * 8];
            float4 a1 = *(const float4*)&As[kk][ty * 8 + 4];
            float4 b  = *(const float4*)&Bs[kk][tx * 4];
            float ar[8] = {a0.x, a0.y, a0.z, a0.w, a1.x, a1.y, a1.z, a1.w};
            float br[4] = {b.x, b.y, b.z, b.w};
            #pragma unroll
            for (int i = 0; i < 8; i++)
                #pragma unroll
                for (int j = 0; j < 4; j++) acc[i][j] += ar[i] * br[j];
        }
        __syncthreads();
    }
    #pragma unroll
    for (int i = 0; i < 8; i++) {
        int gr = bm + ty * 8 + i;
        if (gr < NN)
            *(float4*)(g_ft + gr * 256 + bn + tx * 4) =
                make_float4(acc[i][0], acc[i][1], acc[i][2], acc[i][3]);
    }
}

// ---------------- el/er: per-node dot of ft row with attn_l / attn_r ----------------
__global__ void k_elr(const float* __restrict__ attn_l,
                      const float* __restrict__ attn_r) {
    int w = (blockIdx.x * blockDim.x + threadIdx.x) >> 5;
    int lane = threadIdx.x & 31;
    if (w >= NN) return;
    // element range lane*8 .. lane*8+7; head h = lane>>3; attn offset == lane*8
    const float4* fp = (const float4*)(g_ft + w * 256 + lane * 8);
    float4 x0 = fp[0], x1 = fp[1];
    const float4* alp = (const float4*)(attn_l + lane * 8);
    const float4* arp = (const float4*)(attn_r + lane * 8);
    float4 al0 = alp[0], al1 = alp[1];
    float4 ar0 = arp[0], ar1 = arp[1];
    float pl = x0.x * al0.x + x0.y * al0.y + x0.z * al0.z + x0.w * al0.w
             + x1.x * al1.x + x1.y * al1.y + x1.z * al1.z + x1.w * al1.w;
    float pr = x0.x * ar0.x + x0.y * ar0.y + x0.z * ar0.z + x0.w * ar0.w
             + x1.x * ar1.x + x1.y * ar1.y + x1.z * ar1.z + x1.w * ar1.w;
    #pragma unroll
    for (int o = 4; o > 0; o >>= 1) {
        pl += __shfl_down_sync(0xffffffffu, pl, o);
        pr += __shfl_down_sync(0xffffffffu, pr, o);
    }
    if ((lane & 7) == 0) {
        int h = lane >> 3;
        g_el[w * 4 + h] = pl;
        g_er[w * 4 + h] = pr;
    }
}

// ---------------- CSR build ----------------
__global__ void k_deg(const int* __restrict__ dst) {
    int e = blockIdx.x * blockDim.x + threadIdx.x;
    if (e < NE) atomicAdd(&g_deg[dst[e]], 1);
}

__global__ void k_scan() {              // single block, 1024 threads
    __shared__ int ss[1024];
    const int CH = (NN + 1023) / 1024;  // 49
    int t = threadIdx.x;
    int b = t * CH, e = min(b + CH, NN);
    int s = 0;
    for (int i = b; i < e; i++) s += g_deg[i];
    ss[t] = s;
    __syncthreads();
    for (int o = 1; o < 1024; o <<= 1) {
        int v = (t >= o) ? ss[t - o] : 0;
        __syncthreads();
        ss[t] += v;
        __syncthreads();
    }
    int run = (t == 0) ? 0 : ss[t - 1];
    for (int i = b; i < e; i++) {
        g_off[i] = run;
        g_cur[i] = run;
        run += g_deg[i];
    }
}

__global__ void k_scatter(const int* __restrict__ dst) {
    int e = blockIdx.x * blockDim.x + threadIdx.x;
    if (e < NE) {
        int p = atomicAdd(&g_cur[dst[e]], 1);
        g_eids[p] = e;
    }
}

// ---------------- fused softmax + aggregation: one warp per dst node ----------------
__global__ void k_agg(const int* __restrict__ src,
                      const int* __restrict__ efeat,
                      float* __restrict__ out_rst,
                      float* __restrict__ out_a) {
    int n = (blockIdx.x * blockDim.x + threadIdx.x) >> 5;
    int lane = threadIdx.x & 31;
    if (n >= NN) return;
    int off = g_off[n], dg = g_deg[n];

    float4 erv = *(const float4*)(g_er + n * 4);
    float s0 = 0.f, s1 = 0.f, s2 = 0.f, s3 = 0.f;

    // pass 1: logits -> exp, store raw exp into out_a, accumulate sums
    for (int i = lane; i < dg; i += 32) {
        int e = g_eids[off + i];
        int s = src[e];
        int t = efeat[e];
        float4 elv = *(const float4*)(g_el + s * 4);
        float4 eev = *(const float4*)(g_ee + t * 4);
        float l0 = elv.x + erv.x + eev.x;
        float l1 = elv.y + erv.y + eev.y;
        float l2 = elv.z + erv.z + eev.z;
        float l3 = elv.w + erv.w + eev.w;
        l0 = l0 > 0.f ? l0 : NEG_SLOPE * l0;
        l1 = l1 > 0.f ? l1 : NEG_SLOPE * l1;
        l2 = l2 > 0.f ? l2 : NEG_SLOPE * l2;
        l3 = l3 > 0.f ? l3 : NEG_SLOPE * l3;
        float e0 = expf(l0), e1 = expf(l1), e2 = expf(l2), e3 = expf(l3);
        *(float4*)(out_a + (size_t)e * 4) = make_float4(e0, e1, e2, e3);
        s0 += e0; s1 += e1; s2 += e2; s3 += e3;
    }
    #pragma unroll
    for (int o = 16; o > 0; o >>= 1) {
        s0 += __shfl_xor_sync(0xffffffffu, s0, o);
        s1 += __shfl_xor_sync(0xffffffffu, s1, o);
        s2 += __shfl_xor_sync(0xffffffffu, s2, o);
        s3 += __shfl_xor_sync(0xffffffffu, s3, o);
    }
    float i0 = (dg > 0) ? 1.f / s0 : 0.f;
    float i1 = (dg > 0) ? 1.f / s1 : 0.f;
    float i2 = (dg > 0) ? 1.f / s2 : 0.f;
    float i3 = (dg > 0) ? 1.f / s3 : 0.f;

    // pass 2: normalize own edges (same lane wrote them — no cross-lane hazard)
    for (int i = lane; i < dg; i += 32) {
        int e = g_eids[off + i];
        float4 v = *(const float4*)(out_a + (size_t)e * 4);
        v.x *= i0; v.y *= i1; v.z *= i2; v.w *= i3;
        *(float4*)(out_a + (size_t)e * 4) = v;
    }
    __threadfence_block();
    __syncwarp();

    // pass 3: aggregate — whole warp per edge, coalesced float4 gathers of ft[src]
    float acc[8] = {0.f, 0.f, 0.f, 0.f, 0.f, 0.f, 0.f, 0.f};
    int myh = lane >> 3;
    int boff = lane * 8;
    for (int i = 0; i < dg; i++) {
        int e = g_eids[off + i];
        int s = src[e];
        float a = out_a[(size_t)e * 4 + myh];
        const float4* fp = (const float4*)(g_ft + s * 256 + boff);
        float4 x0 = fp[0], x1 = fp[1];
        acc[0] += a * x0.x; acc[1] += a * x0.y; acc[2] += a * x0.z; acc[3] += a * x0.w;
        acc[4] += a * x1.x; acc[5] += a * x1.y; acc[6] += a * x1.z; acc[7] += a * x1.w;
    }
    float4* op = (float4*)(out_rst + (size_t)n * 256 + boff);
    op[0] = make_float4(acc[0], acc[1], acc[2], acc[3]);
    op[1] = make_float4(acc[4], acc[5], acc[6], acc[7]);
}

// ---------------- launch ----------------
extern "C" void kernel_launch(void* const* d_in, const int* in_sizes, int n_in,
                              void* d_out, int out_size) {
    const float* feat     = (const float*)d_in[0];
    const int*   efeat    = (const int*)  d_in[1];
    const int*   src      = (const int*)  d_in[2];
    const int*   dst      = (const int*)  d_in[3];
    const float* W_fc     = (const float*)d_in[4];
    const float* W_e      = (const float*)d_in[5];
    const float* edge_emb = (const float*)d_in[6];
    const float* attn_l   = (const float*)d_in[7];
    const float* attn_r   = (const float*)d_in[8];
    const float* attn_e   = (const float*)d_in[9];

    float* out_rst = (float*)d_out;
    float* out_a   = (float*)d_out + (size_t)NN * HD;

    void* degp = nullptr;
    cudaGetSymbolAddress(&degp, g_deg);
    cudaMemsetAsync(degp, 0, sizeof(int) * NN, 0);

    k_ee<<<1, 1024>>>(edge_emb, W_e, attn_e);
    k_gemm<<<dim3(4, (NN + 127) / 128), 256>>>(feat, W_fc);
    k_elr<<<(NN * 32 + 255) / 256, 256>>>(attn_l, attn_r);
    k_deg<<<(NE + 255) / 256, 256>>>(dst);
    k_scan<<<1, 1024>>>();
    k_scatter<<<(NE + 255) / 256, 256>>>(dst);
    k_agg<<<(NN * 32 + 255) / 256, 256>>>(src, efeat, out_rst, out_a);
}

// round 3
// speedup vs baseline: 1.2380x; 1.2380x over previous
#include <cuda_runtime.h>
#include <cuda_bf16.h>
#include <cstdint>

#define NN 50000
#define NE 800000
#define H 4
#define D 64
#define HD 256
#define NEG_SLOPE 0.2f

// ---------------- scratch ----------------
__device__ float g_ft[NN * HD];
__device__ float g_el[NN * H];
__device__ float g_er[NN * H];
__device__ float g_ee[8 * H];
__device__ int   g_deg[NN];
__device__ int   g_off[NN];
__device__ int   g_cur[NN];
__device__ int   g_eids[NE];
__device__ __nv_bfloat16 g_Bhi[256 * 256];   // W_fc split, [k][n]
__device__ __nv_bfloat16 g_Blo[256 * 256];

// ---------------- split W_fc into bf16 hi/lo ----------------
__global__ void k_bsplit(const float* __restrict__ B) {
    int i = blockIdx.x * blockDim.x + threadIdx.x;
    if (i < 256 * 256) {
        float v = B[i];
        __nv_bfloat16 h = __float2bfloat16(v);
        g_Bhi[i] = h;
        g_Blo[i] = __float2bfloat16(v - __bfloat162float(h));
    }
}

// ---------------- mma.sync bf16 GEMM (3-pass split) + fused el/er ----------------
// CTA: 256 thr (8 warps, 4x2), tile M=128 N=128, K staged 32/iter.
#define ASTRIDE 80    // 32 bf16 = 64B padded to 80B
#define BSTRIDE 272   // 128 bf16 = 256B padded to 272B

__device__ __forceinline__ void ldsm_x4(uint32_t* r, uint32_t addr) {
    asm volatile("ldmatrix.sync.aligned.m8n8.x4.shared.b16 {%0,%1,%2,%3}, [%4];"
                 : "=r"(r[0]), "=r"(r[1]), "=r"(r[2]), "=r"(r[3]) : "r"(addr));
}
__device__ __forceinline__ void ldsm_x4t(uint32_t* r, uint32_t addr) {
    asm volatile("ldmatrix.sync.aligned.m8n8.x4.trans.shared.b16 {%0,%1,%2,%3}, [%4];"
                 : "=r"(r[0]), "=r"(r[1]), "=r"(r[2]), "=r"(r[3]) : "r"(addr));
}
__device__ __forceinline__ void mma_bf16(float* c, const uint32_t* a, const uint32_t* b) {
    asm volatile(
        "mma.sync.aligned.m16n8k16.row.col.f32.bf16.bf16.f32 "
        "{%0,%1,%2,%3}, {%4,%5,%6,%7}, {%8,%9}, {%0,%1,%2,%3};"
        : "+f"(c[0]), "+f"(c[1]), "+f"(c[2]), "+f"(c[3])
        : "r"(a[0]), "r"(a[1]), "r"(a[2]), "r"(a[3]), "r"(b[0]), "r"(b[1]));
}

__global__ void __launch_bounds__(256, 1) k_gemm_mma(
    const float* __restrict__ A,
    const float* __restrict__ attn_l, const float* __restrict__ attn_r)
{
    __shared__ __align__(16) char sAhi[128 * ASTRIDE];
    __shared__ __align__(16) char sAlo[128 * ASTRIDE];
    __shared__ __align__(16) char sBhi[32 * BSTRIDE];
    __shared__ __align__(16) char sBlo[32 * BSTRIDE];
    __shared__ float s_attn[512];

    int tid = threadIdx.x, wid = tid >> 5, lane = tid & 31;
    int g = lane >> 2, tg = lane & 3;
    int bm = blockIdx.x * 128, bn = blockIdx.y * 128;
    int wm = (wid >> 1) * 32, wn = (wid & 1) * 64;

    uint32_t uAhi = (uint32_t)__cvta_generic_to_shared(sAhi);
    uint32_t uAlo = (uint32_t)__cvta_generic_to_shared(sAlo);
    uint32_t uBhi = (uint32_t)__cvta_generic_to_shared(sBhi);
    uint32_t uBlo = (uint32_t)__cvta_generic_to_shared(sBlo);

    #pragma unroll
    for (int j = tid; j < 512; j += 256)
        s_attn[j] = (j < 256) ? attn_l[j] : attn_r[j - 256];

    float acc[2][8][4];
    #pragma unroll
    for (int am = 0; am < 2; am++)
        #pragma unroll
        for (int nb = 0; nb < 8; nb++)
            #pragma unroll
            for (int q = 0; q < 4; q++) acc[am][nb][q] = 0.f;

    // staging regs
    float4 ra[4];
    uint4 rbh[2], rbl[2];

    // ---- load tile 0 ----
    {
        int k0 = 0;
        #pragma unroll
        for (int j = 0; j < 4; j++) {
            int idx = tid + j * 256;
            int m = idx >> 3, kq = idx & 7;
            int gr = bm + m;
            ra[j] = (gr < NN) ? *(const float4*)(A + (size_t)gr * 256 + k0 + kq * 4)
                              : make_float4(0.f, 0.f, 0.f, 0.f);
        }
        #pragma unroll
        for (int q = 0; q < 2; q++) {
            int idx = tid + q * 256;
            int k = idx >> 4, n8 = idx & 15;
            rbh[q] = ((const uint4*)(g_Bhi + (size_t)(k0 + k) * 256 + bn))[n8];
            rbl[q] = ((const uint4*)(g_Blo + (size_t)(k0 + k) * 256 + bn))[n8];
        }
    }

    for (int it = 0; it < 8; it++) {
        // ---- store staged regs to smem (A: split hi/lo) ----
        #pragma unroll
        for (int j = 0; j < 4; j++) {
            int idx = tid + j * 256;
            int m = idx >> 3, kq = idx & 7;
            float4 v = ra[j];
            __nv_bfloat16 hx = __float2bfloat16(v.x), hy = __float2bfloat16(v.y);
            __nv_bfloat16 hz = __float2bfloat16(v.z), hw = __float2bfloat16(v.w);
            __nv_bfloat162 hi0(hx, hy), hi1(hz, hw);
            __nv_bfloat162 lo0 = __floats2bfloat162_rn(v.x - __bfloat162float(hx),
                                                       v.y - __bfloat162float(hy));
            __nv_bfloat162 lo1 = __floats2bfloat162_rn(v.z - __bfloat162float(hz),
                                                       v.w - __bfloat162float(hw));
            char* ph = sAhi + m * ASTRIDE + kq * 8;
            char* pl = sAlo + m * ASTRIDE + kq * 8;
            *(__nv_bfloat162*)(ph)     = hi0;
            *(__nv_bfloat162*)(ph + 4) = hi1;
            *(__nv_bfloat162*)(pl)     = lo0;
            *(__nv_bfloat162*)(pl + 4) = lo1;
        }
        #pragma unroll
        for (int q = 0; q < 2; q++) {
            int idx = tid + q * 256;
            int k = idx >> 4, n8 = idx & 15;
            *(uint4*)(sBhi + k * BSTRIDE + n8 * 16) = rbh[q];
            *(uint4*)(sBlo + k * BSTRIDE + n8 * 16) = rbl[q];
        }
        __syncthreads();

        // ---- prefetch next tile ----
        if (it < 7) {
            int k0 = (it + 1) * 32;
            #pragma unroll
            for (int j = 0; j < 4; j++) {
                int idx = tid + j * 256;
                int m = idx >> 3, kq = idx & 7;
                int gr = bm + m;
                ra[j] = (gr < NN) ? *(const float4*)(A + (size_t)gr * 256 + k0 + kq * 4)
                                  : make_float4(0.f, 0.f, 0.f, 0.f);
            }
            #pragma unroll
            for (int q = 0; q < 2; q++) {
                int idx = tid + q * 256;
                int k = idx >> 4, n8 = idx & 15;
                rbh[q] = ((const uint4*)(g_Bhi + (size_t)(k0 + k) * 256 + bn))[n8];
                rbl[q] = ((const uint4*)(g_Blo + (size_t)(k0 + k) * 256 + bn))[n8];
            }
        }

        // ---- compute: 2 k16 steps ----
        #pragma unroll
        for (int ks = 0; ks < 2; ks++) {
            uint32_t ah[2][4], al[2][4];
            #pragma unroll
            for (int am = 0; am < 2; am++) {
                uint32_t row = wm + am * 16 + (lane & 7) + ((lane >> 3) & 1) * 8;
                uint32_t off = row * ASTRIDE + ks * 32 + (lane >> 4) * 16;
                ldsm_x4(ah[am], uAhi + off);
                ldsm_x4(al[am], uAlo + off);
            }
            uint32_t bh[8][2];
            #pragma unroll
            for (int ng = 0; ng < 2; ng++)
                #pragma unroll
                for (int kh = 0; kh < 2; kh++) {
                    uint32_t r[4];
                    uint32_t off = (ks * 16 + kh * 8 + (lane & 7)) * BSTRIDE
                                 + wn * 2 + ng * 64 + (lane >> 3) * 16;
                    ldsm_x4t(r, uBhi + off);
                    #pragma unroll
                    for (int jj = 0; jj < 4; jj++) bh[ng * 4 + jj][kh] = r[jj];
                }
            #pragma unroll
            for (int am = 0; am < 2; am++)
                #pragma unroll
                for (int nb = 0; nb < 8; nb++) mma_bf16(acc[am][nb], ah[am], bh[nb]);
            #pragma unroll
            for (int am = 0; am < 2; am++)
                #pragma unroll
                for (int nb = 0; nb < 8; nb++) mma_bf16(acc[am][nb], al[am], bh[nb]);
            uint32_t bl[8][2];
            #pragma unroll
            for (int ng = 0; ng < 2; ng++)
                #pragma unroll
                for (int kh = 0; kh < 2; kh++) {
                    uint32_t r[4];
                    uint32_t off = (ks * 16 + kh * 8 + (lane & 7)) * BSTRIDE
                                 + wn * 2 + ng * 64 + (lane >> 3) * 16;
                    ldsm_x4t(r, uBlo + off);
                    #pragma unroll
                    for (int jj = 0; jj < 4; jj++) bl[ng * 4 + jj][kh] = r[jj];
                }
            #pragma unroll
            for (int am = 0; am < 2; am++)
                #pragma unroll
                for (int nb = 0; nb < 8; nb++) mma_bf16(acc[am][nb], ah[am], bl[nb]);
        }
        __syncthreads();
    }

    // ---- epilogue: store g_ft + fused el/er (warp owns head h) ----
    int h = blockIdx.y * 2 + (wid & 1);
    float elp[2][2] = {{0.f, 0.f}, {0.f, 0.f}};
    float erp[2][2] = {{0.f, 0.f}, {0.f, 0.f}};

    #pragma unroll
    for (int am = 0; am < 2; am++) {
        #pragma unroll
        for (int rh = 0; rh < 2; rh++) {
            int row = bm + wm + am * 16 + g + rh * 8;
            if (row < NN) {
                #pragma unroll
                for (int nb = 0; nb < 8; nb++) {
                    float c0 = acc[am][nb][rh * 2 + 0];
                    float c1 = acc[am][nb][rh * 2 + 1];
                    int col = bn + wn + nb * 8 + 2 * tg;
                    *(float2*)(g_ft + (size_t)row * 256 + col) = make_float2(c0, c1);
                    int ch = nb * 8 + 2 * tg;   // col within head
                    elp[am][rh] += c0 * s_attn[h * 64 + ch]     + c1 * s_attn[h * 64 + ch + 1];
                    erp[am][rh] += c0 * s_attn[256 + h * 64 + ch] + c1 * s_attn[256 + h * 64 + ch + 1];
                }
            }
        }
    }
    #pragma unroll
    for (int am = 0; am < 2; am++)
        #pragma unroll
        for (int rh = 0; rh < 2; rh++) {
            float e1 = elp[am][rh], e2 = erp[am][rh];
            #pragma unroll
            for (int o = 1; o < 4; o <<= 1) {
                e1 += __shfl_xor_sync(0xffffffffu, e1, o);
                e2 += __shfl_xor_sync(0xffffffffu, e2, o);
            }
            if (tg == 0) {
                int row = bm + wm + am * 16 + g + rh * 8;
                if (row < NN) {
                    g_el[row * 4 + h] = e1;
                    g_er[row * 4 + h] = e2;
                }
            }
        }
}

// ---------------- ee table ----------------
__global__ void k_ee(const float* __restrict__ edge_emb,
                     const float* __restrict__ W_e,
                     const float* __restrict__ attn_e) {
    int w = threadIdx.x >> 5;
    int lane = threadIdx.x & 31;
    if (w >= 32) return;
    int t = w >> 2, h = w & 3;
    float acc0 = 0.f, acc1 = 0.f;
    int f0 = lane, f1 = lane + 32;
    #pragma unroll 4
    for (int k = 0; k < 64; k++) {
        float ek = edge_emb[t * 64 + k];
        acc0 += ek * W_e[k * 256 + h * 64 + f0];
        acc1 += ek * W_e[k * 256 + h * 64 + f1];
    }
    float v = acc0 * attn_e[h * 64 + f0] + acc1 * attn_e[h * 64 + f1];
    #pragma unroll
    for (int o = 16; o > 0; o >>= 1) v += __shfl_xor_sync(0xffffffffu, v, o);
    if (lane == 0) g_ee[t * 4 + h] = v;
}

// ---------------- CSR build ----------------
__global__ void k_deg(const int* __restrict__ dst) {
    int e = blockIdx.x * blockDim.x + threadIdx.x;
    if (e < NE) atomicAdd(&g_deg[dst[e]], 1);
}

__global__ void k_scan() {
    __shared__ int ss[1024];
    const int CH = (NN + 1023) / 1024;
    int t = threadIdx.x;
    int b = t * CH, e = min(b + CH, NN);
    int s = 0;
    for (int i = b; i < e; i++) s += g_deg[i];
    ss[t] = s;
    __syncthreads();
    for (int o = 1; o < 1024; o <<= 1) {
        int v = (t >= o) ? ss[t - o] : 0;
        __syncthreads();
        ss[t] += v;
        __syncthreads();
    }
    int run = (t == 0) ? 0 : ss[t - 1];
    for (int i = b; i < e; i++) {
        g_off[i] = run;
        g_cur[i] = run;
        run += g_deg[i];
    }
}

__global__ void k_scatter(const int* __restrict__ dst) {
    int e = blockIdx.x * blockDim.x + threadIdx.x;
    if (e < NE) {
        int p = atomicAdd(&g_cur[dst[e]], 1);
        g_eids[p] = e;
    }
}

// ---------------- fused softmax + aggregation ----------------
__global__ void k_agg(const int* __restrict__ src,
                      const int* __restrict__ efeat,
                      float* __restrict__ out_rst,
                      float* __restrict__ out_a) {
    int n = (blockIdx.x * blockDim.x + threadIdx.x) >> 5;
    int lane = threadIdx.x & 31;
    if (n >= NN) return;
    int off = g_off[n], dg = g_deg[n];

    float4 erv = *(const float4*)(g_er + n * 4);
    float s0 = 0.f, s1 = 0.f, s2 = 0.f, s3 = 0.f;

    for (int i = lane; i < dg; i += 32) {
        int e = g_eids[off + i];
        int s = src[e];
        int t = efeat[e];
        float4 elv = *(const float4*)(g_el + s * 4);
        float4 eev = *(const float4*)(g_ee + t * 4);
        float l0 = elv.x + erv.x + eev.x;
        float l1 = elv.y + erv.y + eev.y;
        float l2 = elv.z + erv.z + eev.z;
        float l3 = elv.w + erv.w + eev.w;
        l0 = l0 > 0.f ? l0 : NEG_SLOPE * l0;
        l1 = l1 > 0.f ? l1 : NEG_SLOPE * l1;
        l2 = l2 > 0.f ? l2 : NEG_SLOPE * l2;
        l3 = l3 > 0.f ? l3 : NEG_SLOPE * l3;
        float e0 = expf(l0), e1 = expf(l1), e2 = expf(l2), e3 = expf(l3);
        *(float4*)(out_a + (size_t)e * 4) = make_float4(e0, e1, e2, e3);
        s0 += e0; s1 += e1; s2 += e2; s3 += e3;
    }
    #pragma unroll
    for (int o = 16; o > 0; o >>= 1) {
        s0 += __shfl_xor_sync(0xffffffffu, s0, o);
        s1 += __shfl_xor_sync(0xffffffffu, s1, o);
        s2 += __shfl_xor_sync(0xffffffffu, s2, o);
        s3 += __shfl_xor_sync(0xffffffffu, s3, o);
    }
    float i0 = (dg > 0) ? 1.f / s0 : 0.f;
    float i1 = (dg > 0) ? 1.f / s1 : 0.f;
    float i2 = (dg > 0) ? 1.f / s2 : 0.f;
    float i3 = (dg > 0) ? 1.f / s3 : 0.f;

    for (int i = lane; i < dg; i += 32) {
        int e = g_eids[off + i];
        float4 v = *(const float4*)(out_a + (size_t)e * 4);
        v.x *= i0; v.y *= i1; v.z *= i2; v.w *= i3;
        *(float4*)(out_a + (size_t)e * 4) = v;
    }
    __threadfence_block();
    __syncwarp();

    float acc[8] = {0.f, 0.f, 0.f, 0.f, 0.f, 0.f, 0.f, 0.f};
    int myh = lane >> 3;
    int boff = lane * 8;
    for (int i = 0; i < dg; i++) {
        int e = g_eids[off + i];
        int s = src[e];
        float a = out_a[(size_t)e * 4 + myh];
        const float4* fp = (const float4*)(g_ft + (size_t)s * 256 + boff);
        float4 x0 = fp[0], x1 = fp[1];
        acc[0] += a * x0.x; acc[1] += a * x0.y; acc[2] += a * x0.z; acc[3] += a * x0.w;
        acc[4] += a * x1.x; acc[5] += a * x1.y; acc[6] += a * x1.z; acc[7] += a * x1.w;
    }
    float4* op = (float4*)(out_rst + (size_t)n * 256 + boff);
    op[0] = make_float4(acc[0], acc[1], acc[2], acc[3]);
    op[1] = make_float4(acc[4], acc[5], acc[6], acc[7]);
}

// ---------------- launch ----------------
extern "C" void kernel_launch(void* const* d_in, const int* in_sizes, int n_in,
                              void* d_out, int out_size) {
    const float* feat     = (const float*)d_in[0];
    const int*   efeat    = (const int*)  d_in[1];
    const int*   src      = (const int*)  d_in[2];
    const int*   dst      = (const int*)  d_in[3];
    const float* W_fc     = (const float*)d_in[4];
    const float* W_e      = (const float*)d_in[5];
    const float* edge_emb = (const float*)d_in[6];
    const float* attn_l   = (const float*)d_in[7];
    const float* attn_r   = (const float*)d_in[8];
    const float* attn_e   = (const float*)d_in[9];

    float* out_rst = (float*)d_out;
    float* out_a   = (float*)d_out + (size_t)NN * HD;

    void* degp = nullptr;
    cudaGetSymbolAddress(&degp, g_deg);
    cudaMemsetAsync(degp, 0, sizeof(int) * NN, 0);

    k_bsplit<<<256, 256>>>(W_fc);
    k_ee<<<1, 1024>>>(edge_emb, W_e, attn_e);
    k_gemm_mma<<<dim3((NN + 127) / 128, 2), 256>>>(feat, attn_l, attn_r);
    k_deg<<<(NE + 255) / 256, 256>>>(dst);
    k_scan<<<1, 1024>>>();
    k_scatter<<<(NE + 255) / 256, 256>>>(dst);
    k_agg<<<(NN * 32 + 255) / 256, 256>>>(src, efeat, out_rst, out_a);
}

// round 4
// speedup vs baseline: 1.2862x; 1.0390x over previous
#include <cuda_runtime.h>
#include <cuda_bf16.h>
#include <cstdint>

#define NN 50000
#define NE 800000
#define H 4
#define D 64
#define HD 256
#define NEG_SLOPE 0.2f

// ---------------- scratch ----------------
__device__ float g_ft[NN * HD];
__device__ float g_el[NN * H];
__device__ float g_er[NN * H];
__device__ float g_ee[8 * H];
__device__ int   g_deg[NN];
__device__ int   g_off[NN];
__device__ int   g_cur[NN];
__device__ int   g_eids[NE];
__device__ __nv_bfloat16 g_Ahi[NN * 256];
__device__ __nv_bfloat16 g_Alo[NN * 256];
__device__ __nv_bfloat16 g_Bhi[256 * 256];
__device__ __nv_bfloat16 g_Blo[256 * 256];

// ---------------- fused prep: A-split | B-split | ee | deg ----------------
// blocks [0,12500): feat split (NN*64 float4)
// blocks [12500,12564): W_fc split (16384 float4)
// blocks [12564,12568): ee table (8 warps/block, 1 (t,h) pair per warp)
// blocks [12568,15693): degree count
__global__ void k_prep(const float* __restrict__ feat, const float* __restrict__ W_fc,
                       const float* __restrict__ edge_emb, const float* __restrict__ W_e,
                       const float* __restrict__ attn_e, const int* __restrict__ dst) {
    int b = blockIdx.x;
    if (b < 12500) {
        int i = b * 256 + threadIdx.x;          // float4 index
        float4 v = ((const float4*)feat)[i];
        __nv_bfloat16 hx = __float2bfloat16(v.x), hy = __float2bfloat16(v.y);
        __nv_bfloat16 hz = __float2bfloat16(v.z), hw = __float2bfloat16(v.w);
        __nv_bfloat162 h0(hx, hy), h1(hz, hw);
        __nv_bfloat162 l0 = __floats2bfloat162_rn(v.x - __bfloat162float(hx),
                                                  v.y - __bfloat162float(hy));
        __nv_bfloat162 l1 = __floats2bfloat162_rn(v.z - __bfloat162float(hz),
                                                  v.w - __bfloat162float(hw));
        uint2 hp, lp;
        hp.x = *(uint32_t*)&h0; hp.y = *(uint32_t*)&h1;
        lp.x = *(uint32_t*)&l0; lp.y = *(uint32_t*)&l1;
        *(uint2*)(g_Ahi + 4 * (size_t)i) = hp;
        *(uint2*)(g_Alo + 4 * (size_t)i) = lp;
    } else if (b < 12564) {
        int i = (b - 12500) * 256 + threadIdx.x;
        float4 v = ((const float4*)W_fc)[i];
        __nv_bfloat16 hx = __float2bfloat16(v.x), hy = __float2bfloat16(v.y);
        __nv_bfloat16 hz = __float2bfloat16(v.z), hw = __float2bfloat16(v.w);
        __nv_bfloat162 h0(hx, hy), h1(hz, hw);
        __nv_bfloat162 l0 = __floats2bfloat162_rn(v.x - __bfloat162float(hx),
                                                  v.y - __bfloat162float(hy));
        __nv_bfloat162 l1 = __floats2bfloat162_rn(v.z - __bfloat162float(hz),
                                                  v.w - __bfloat162float(hw));
        uint2 hp, lp;
        hp.x = *(uint32_t*)&h0; hp.y = *(uint32_t*)&h1;
        lp.x = *(uint32_t*)&l0; lp.y = *(uint32_t*)&l1;
        *(uint2*)(g_Bhi + 4 * (size_t)i) = hp;
        *(uint2*)(g_Blo + 4 * (size_t)i) = lp;
    } else if (b < 12568) {
        int p = (b - 12564) * 8 + (threadIdx.x >> 5);  // pair 0..31
        int lane = threadIdx.x & 31;
        int t = p >> 2, h = p & 3;
        float acc0 = 0.f, acc1 = 0.f;
        int f0 = lane, f1 = lane + 32;
        #pragma unroll 4
        for (int k = 0; k < 64; k++) {
            float ek = edge_emb[t * 64 + k];
            acc0 += ek * W_e[k * 256 + h * 64 + f0];
            acc1 += ek * W_e[k * 256 + h * 64 + f1];
        }
        float v = acc0 * attn_e[h * 64 + f0] + acc1 * attn_e[h * 64 + f1];
        #pragma unroll
        for (int o = 16; o > 0; o >>= 1) v += __shfl_xor_sync(0xffffffffu, v, o);
        if (lane == 0) g_ee[t * 4 + h] = v;
    } else {
        int e = (b - 12568) * 256 + threadIdx.x;
        if (e < NE) atomicAdd(&g_deg[dst[e]], 1);
    }
}

// ---------------- mma.sync bf16 GEMM (3-pass split), cp.async pipelined ----------------
#define ASTRIDE 80
#define BSTRIDE 272
#define ABUF 10240   // 128*80
#define BBUF 8704    // 32*272
#define SM_TOT2 (4*ABUF + 4*BBUF + 2048)

__device__ __forceinline__ void cpa16(uint32_t dst, const void* src) {
    asm volatile("cp.async.ca.shared.global [%0], [%1], 16;" :: "r"(dst), "l"(src));
}
__device__ __forceinline__ void ldsm_x4(uint32_t* r, uint32_t addr) {
    asm volatile("ldmatrix.sync.aligned.m8n8.x4.shared.b16 {%0,%1,%2,%3}, [%4];"
                 : "=r"(r[0]), "=r"(r[1]), "=r"(r[2]), "=r"(r[3]) : "r"(addr));
}
__device__ __forceinline__ void ldsm_x4t(uint32_t* r, uint32_t addr) {
    asm volatile("ldmatrix.sync.aligned.m8n8.x4.trans.shared.b16 {%0,%1,%2,%3}, [%4];"
                 : "=r"(r[0]), "=r"(r[1]), "=r"(r[2]), "=r"(r[3]) : "r"(addr));
}
__device__ __forceinline__ void mma_bf16(float* c, const uint32_t* a, const uint32_t* b) {
    asm volatile(
        "mma.sync.aligned.m16n8k16.row.col.f32.bf16.bf16.f32 "
        "{%0,%1,%2,%3}, {%4,%5,%6,%7}, {%8,%9}, {%0,%1,%2,%3};"
        : "+f"(c[0]), "+f"(c[1]), "+f"(c[2]), "+f"(c[3])
        : "r"(a[0]), "r"(a[1]), "r"(a[2]), "r"(a[3]), "r"(b[0]), "r"(b[1]));
}

__global__ void __launch_bounds__(256, 2) k_gemm2(
    const float* __restrict__ attn_l, const float* __restrict__ attn_r)
{
    extern __shared__ __align__(16) char smem[];
    uint32_t uA  = (uint32_t)__cvta_generic_to_shared(smem);
    uint32_t uAl = uA + 2 * ABUF;
    uint32_t uBh = uA + 4 * ABUF;
    uint32_t uBl = uBh + 2 * BBUF;
    float* s_attn = (float*)(smem + 4 * ABUF + 4 * BBUF);

    int tid = threadIdx.x, wid = tid >> 5, lane = tid & 31;
    int g = lane >> 2, tg = lane & 3;
    int bm = blockIdx.x * 128, bn = blockIdx.y * 128;
    int wm = (wid >> 1) * 32, wn = (wid & 1) * 64;

    #pragma unroll
    for (int j = tid; j < 512; j += 256)
        s_attn[j] = (j < 256) ? attn_l[j] : attn_r[j - 256];

    float acc[2][8][4];
    #pragma unroll
    for (int am = 0; am < 2; am++)
        #pragma unroll
        for (int nb = 0; nb < 8; nb++)
            #pragma unroll
            for (int q = 0; q < 4; q++) acc[am][nb][q] = 0.f;

    // tile loader: K chunk it -> buffer bf
    auto load_tile = [&](int it, int bf) {
        int k0 = it * 32;
        #pragma unroll
        for (int j = 0; j < 2; j++) {          // A: 512 chunks of 16B
            int idx = tid + j * 256;
            int row = idx >> 2, q = idx & 3;
            int gr = min(bm + row, NN - 1);
            uint32_t d = bf * ABUF + row * ASTRIDE + q * 16;
            const __nv_bfloat16* s = g_Ahi + (size_t)gr * 256 + k0 + q * 8;
            cpa16(uA + d, s);
            cpa16(uAl + d, g_Alo + (size_t)gr * 256 + k0 + q * 8);
        }
        #pragma unroll
        for (int j = 0; j < 2; j++) {          // B: 512 chunks of 16B
            int idx = tid + j * 256;
            int k = idx >> 4, n16 = idx & 15;
            uint32_t d = bf * BBUF + k * BSTRIDE + n16 * 16;
            cpa16(uBh + d, g_Bhi + (size_t)(k0 + k) * 256 + bn + n16 * 8);
            cpa16(uBl + d, g_Blo + (size_t)(k0 + k) * 256 + bn + n16 * 8);
        }
    };

    load_tile(0, 0);
    asm volatile("cp.async.commit_group;" ::: "memory");

    for (int it = 0; it < 8; it++) {
        if (it < 7) {
            load_tile(it + 1, (it + 1) & 1);
            asm volatile("cp.async.commit_group;" ::: "memory");
            asm volatile("cp.async.wait_group 1;" ::: "memory");
        } else {
            asm volatile("cp.async.wait_group 0;" ::: "memory");
        }
        __syncthreads();

        uint32_t aoff = (it & 1) * ABUF, boff = (it & 1) * BBUF;
        #pragma unroll
        for (int ks = 0; ks < 2; ks++) {
            uint32_t ah[2][4], al[2][4];
            #pragma unroll
            for (int am = 0; am < 2; am++) {
                uint32_t row = wm + am * 16 + (lane & 7) + ((lane >> 3) & 1) * 8;
                uint32_t off = aoff + row * ASTRIDE + ks * 32 + (lane >> 4) * 16;
                ldsm_x4(ah[am], uA + off);
                ldsm_x4(al[am], uAl + off);
            }
            uint32_t bh[8][2];
            #pragma unroll
            for (int ng = 0; ng < 2; ng++)
                #pragma unroll
                for (int kh = 0; kh < 2; kh++) {
                    uint32_t r[4];
                    uint32_t off = boff + (ks * 16 + kh * 8 + (lane & 7)) * BSTRIDE
                                 + wn * 2 + ng * 64 + (lane >> 3) * 16;
                    ldsm_x4t(r, uBh + off);
                    #pragma unroll
                    for (int jj = 0; jj < 4; jj++) bh[ng * 4 + jj][kh] = r[jj];
                }
            #pragma unroll
            for (int am = 0; am < 2; am++)
                #pragma unroll
                for (int nb = 0; nb < 8; nb++) mma_bf16(acc[am][nb], ah[am], bh[nb]);
            #pragma unroll
            for (int am = 0; am < 2; am++)
                #pragma unroll
                for (int nb = 0; nb < 8; nb++) mma_bf16(acc[am][nb], al[am], bh[nb]);
            uint32_t bl[8][2];
            #pragma unroll
            for (int ng = 0; ng < 2; ng++)
                #pragma unroll
                for (int kh = 0; kh < 2; kh++) {
                    uint32_t r[4];
                    uint32_t off = boff + (ks * 16 + kh * 8 + (lane & 7)) * BSTRIDE
                                 + wn * 2 + ng * 64 + (lane >> 3) * 16;
                    ldsm_x4t(r, uBl + off);
                    #pragma unroll
                    for (int jj = 0; jj < 4; jj++) bl[ng * 4 + jj][kh] = r[jj];
                }
            #pragma unroll
            for (int am = 0; am < 2; am++)
                #pragma unroll
                for (int nb = 0; nb < 8; nb++) mma_bf16(acc[am][nb], ah[am], bl[nb]);
        }
        __syncthreads();
    }

    // ---- epilogue: store g_ft + fused el/er (warp owns head h) ----
    int h = blockIdx.y * 2 + (wid & 1);
    float elp[2][2] = {{0.f, 0.f}, {0.f, 0.f}};
    float erp[2][2] = {{0.f, 0.f}, {0.f, 0.f}};

    #pragma unroll
    for (int am = 0; am < 2; am++) {
        #pragma unroll
        for (int rh = 0; rh < 2; rh++) {
            int row = bm + wm + am * 16 + g + rh * 8;
            if (row < NN) {
                #pragma unroll
                for (int nb = 0; nb < 8; nb++) {
                    float c0 = acc[am][nb][rh * 2 + 0];
                    float c1 = acc[am][nb][rh * 2 + 1];
                    int col = bn + wn + nb * 8 + 2 * tg;
                    *(float2*)(g_ft + (size_t)row * 256 + col) = make_float2(c0, c1);
                    int ch = nb * 8 + 2 * tg;
                    elp[am][rh] += c0 * s_attn[h * 64 + ch]       + c1 * s_attn[h * 64 + ch + 1];
                    erp[am][rh] += c0 * s_attn[256 + h * 64 + ch] + c1 * s_attn[256 + h * 64 + ch + 1];
                }
            }
        }
    }
    #pragma unroll
    for (int am = 0; am < 2; am++)
        #pragma unroll
        for (int rh = 0; rh < 2; rh++) {
            float e1 = elp[am][rh], e2 = erp[am][rh];
            #pragma unroll
            for (int o = 1; o < 4; o <<= 1) {
                e1 += __shfl_xor_sync(0xffffffffu, e1, o);
                e2 += __shfl_xor_sync(0xffffffffu, e2, o);
            }
            if (tg == 0) {
                int row = bm + wm + am * 16 + g + rh * 8;
                if (row < NN) {
                    g_el[row * 4 + h] = e1;
                    g_er[row * 4 + h] = e2;
                }
            }
        }
}

// ---------------- CSR build ----------------
__global__ void k_scan() {
    __shared__ int ss[1024];
    const int CH = (NN + 1023) / 1024;
    int t = threadIdx.x;
    int b = t * CH, e = min(b + CH, NN);
    int s = 0;
    for (int i = b; i < e; i++) s += g_deg[i];
    ss[t] = s;
    __syncthreads();
    for (int o = 1; o < 1024; o <<= 1) {
        int v = (t >= o) ? ss[t - o] : 0;
        __syncthreads();
        ss[t] += v;
        __syncthreads();
    }
    int run = (t == 0) ? 0 : ss[t - 1];
    for (int i = b; i < e; i++) {
        g_off[i] = run;
        g_cur[i] = run;
        run += g_deg[i];
    }
}

__global__ void k_scatter(const int* __restrict__ dst) {
    int e = blockIdx.x * blockDim.x + threadIdx.x;
    if (e < NE) {
        int p = atomicAdd(&g_cur[dst[e]], 1);
        g_eids[p] = e;
    }
}

__global__ void k_zerodeg() {
    int i = blockIdx.x * blockDim.x + threadIdx.x;
    if (i < NN) g_deg[i] = 0;
}

// ---------------- fused softmax + aggregation ----------------
__global__ void k_agg(const int* __restrict__ src,
                      const int* __restrict__ efeat,
                      float* __restrict__ out_rst,
                      float* __restrict__ out_a) {
    int n = (blockIdx.x * blockDim.x + threadIdx.x) >> 5;
    int lane = threadIdx.x & 31;
    if (n >= NN) return;
    int off = g_off[n], dg = g_deg[n];

    float4 erv = *(const float4*)(g_er + n * 4);
    float s0 = 0.f, s1 = 0.f, s2 = 0.f, s3 = 0.f;

    for (int i = lane; i < dg; i += 32) {
        int e = g_eids[off + i];
        int s = src[e];
        int t = efeat[e];
        float4 elv = *(const float4*)(g_el + s * 4);
        float4 eev = *(const float4*)(g_ee + t * 4);
        float l0 = elv.x + erv.x + eev.x;
        float l1 = elv.y + erv.y + eev.y;
        float l2 = elv.z + erv.z + eev.z;
        float l3 = elv.w + erv.w + eev.w;
        l0 = l0 > 0.f ? l0 : NEG_SLOPE * l0;
        l1 = l1 > 0.f ? l1 : NEG_SLOPE * l1;
        l2 = l2 > 0.f ? l2 : NEG_SLOPE * l2;
        l3 = l3 > 0.f ? l3 : NEG_SLOPE * l3;
        float e0 = expf(l0), e1 = expf(l1), e2 = expf(l2), e3 = expf(l3);
        *(float4*)(out_a + (size_t)e * 4) = make_float4(e0, e1, e2, e3);
        s0 += e0; s1 += e1; s2 += e2; s3 += e3;
    }
    #pragma unroll
    for (int o = 16; o > 0; o >>= 1) {
        s0 += __shfl_xor_sync(0xffffffffu, s0, o);
        s1 += __shfl_xor_sync(0xffffffffu, s1, o);
        s2 += __shfl_xor_sync(0xffffffffu, s2, o);
        s3 += __shfl_xor_sync(0xffffffffu, s3, o);
    }
    float i0 = (dg > 0) ? 1.f / s0 : 0.f;
    float i1 = (dg > 0) ? 1.f / s1 : 0.f;
    float i2 = (dg > 0) ? 1.f / s2 : 0.f;
    float i3 = (dg > 0) ? 1.f / s3 : 0.f;

    for (int i = lane; i < dg; i += 32) {
        int e = g_eids[off + i];
        float4 v = *(const float4*)(out_a + (size_t)e * 4);
        v.x *= i0; v.y *= i1; v.z *= i2; v.w *= i3;
        *(float4*)(out_a + (size_t)e * 4) = v;
    }
    __threadfence_block();
    __syncwarp();

    float acc[8] = {0.f, 0.f, 0.f, 0.f, 0.f, 0.f, 0.f, 0.f};
    int myh = lane >> 3;
    int boff = lane * 8;
    #pragma unroll 2
    for (int i = 0; i < dg; i++) {
        int e = g_eids[off + i];
        int s = src[e];
        float a = out_a[(size_t)e * 4 + myh];
        const float4* fp = (const float4*)(g_ft + (size_t)s * 256 + boff);
        float4 x0 = fp[0], x1 = fp[1];
        acc[0] += a * x0.x; acc[1] += a * x0.y; acc[2] += a * x0.z; acc[3] += a * x0.w;
        acc[4] += a * x1.x; acc[5] += a * x1.y; acc[6] += a * x1.z; acc[7] += a * x1.w;
    }
    float4* op = (float4*)(out_rst + (size_t)n * 256 + boff);
    op[0] = make_float4(acc[0], acc[1], acc[2], acc[3]);
    op[1] = make_float4(acc[4], acc[5], acc[6], acc[7]);
}

// ---------------- launch ----------------
extern "C" void kernel_launch(void* const* d_in, const int* in_sizes, int n_in,
                              void* d_out, int out_size) {
    const float* feat     = (const float*)d_in[0];
    const int*   efeat    = (const int*)  d_in[1];
    const int*   src      = (const int*)  d_in[2];
    const int*   dst      = (const int*)  d_in[3];
    const float* W_fc     = (const float*)d_in[4];
    const float* W_e      = (const float*)d_in[5];
    const float* edge_emb = (const float*)d_in[6];
    const float* attn_l   = (const float*)d_in[7];
    const float* attn_r   = (const float*)d_in[8];
    const float* attn_e   = (const float*)d_in[9];

    float* out_rst = (float*)d_out;
    float* out_a   = (float*)d_out + (size_t)NN * HD;

    cudaFuncSetAttribute(k_gemm2, cudaFuncAttributeMaxDynamicSharedMemorySize, SM_TOT2);

    // launch order puts k_agg at slot 5 (the slot ncu captures)
    k_prep<<<15693, 256>>>(feat, W_fc, edge_emb, W_e, attn_e, dst);   // 1
    k_scan<<<1, 1024>>>();                                            // 2
    k_scatter<<<3125, 256>>>(dst);                                    // 3
    k_gemm2<<<dim3(391, 2), 256, SM_TOT2>>>(attn_l, attn_r);          // 4
    k_agg<<<(NN * 32 + 255) / 256, 256>>>(src, efeat, out_rst, out_a);// 5
    k_zerodeg<<<(NN + 255) / 256, 256>>>();                           // 6
}